// round 2
// baseline (speedup 1.0000x reference)
#include <cuda_runtime.h>
#include <math.h>

#define PS 16
#define PH 64
#define PW 64
#define NPATCH (PH*PW)
#define NB 32
#define IH 1024
#define IW 1024
#define ROWF4 (IW/4)   // 256 float4 per image row

// Scratch (no device allocation allowed)
__device__ float g_qual [NB*NPATCH];
__device__ float g_pmean[NB*NPATCH];
__device__ int   g_code [NPATCH];
__device__ float g_scale[NPATCH];
__device__ float g_mpp  [NPATCH];

// ---------------------------------------------------------------------------
// Kernel 1: per-(batch, patch) quality + mean. float4 loads.
// Grid: (64, 32) = (patch-row, batch). Block 256 threads covers the full
// 1024-col strip (one float4 per thread per row). Patch = 4 consecutive lanes.
// ---------------------------------------------------------------------------
__global__ void stats_kernel(const float4* __restrict__ img) {
    const int tx = threadIdx.x;
    const int sy = blockIdx.x;           // patch row
    const int b  = blockIdx.y;

    const float4* base = img + ((size_t)b * IH + (size_t)sy * PS) * ROWF4 + tx;

    float s = 0.f, ss = 0.f;
#pragma unroll
    for (int y = 0; y < PS; ++y) {
        float4 v = base[(size_t)y * ROWF4];
        s  += (v.x + v.y) + (v.z + v.w);
        ss  = fmaf(v.x, v.x, ss);
        ss  = fmaf(v.y, v.y, ss);
        ss  = fmaf(v.z, v.z, ss);
        ss  = fmaf(v.w, v.w, ss);
    }
    // reduce across the 4 lanes of each patch
#pragma unroll
    for (int off = 2; off >= 1; off >>= 1) {
        s  += __shfl_down_sync(0xffffffffu, s,  off, 4);
        ss += __shfl_down_sync(0xffffffffu, ss, off, 4);
    }
    if ((tx & 3) == 0) {
        float mean = s * (1.0f / 256.0f);
        float var  = (ss - s * s * (1.0f / 256.0f)) * (1.0f / 255.0f); // ddof=1
        var = fmaxf(var, 0.0f);
        float std_ = sqrtf(var);
        float iq   = 1.0f - 2.0f * fabsf(mean - 0.5f);
        float quality = (std_ + iq + var) * (1.0f / 3.0f);
        int px = tx >> 2;                // patch col 0..63
        int p  = sy * PW + px;
        g_qual [b * NPATCH + p] = quality;
        g_pmean[b * NPATCH + p] = mean;
    }
}

// ---------------------------------------------------------------------------
// Kernel 2: per-patch code/scale/mpp. Deterministic batch reduction.
// ---------------------------------------------------------------------------
__global__ void code_kernel(const float* __restrict__ r_strong,
                            const float* __restrict__ r_drop,
                            const float* __restrict__ r_else,
                            const float* __restrict__ bright_f,
                            const float* __restrict__ contrast_f,
                            const float* __restrict__ slight_f,
                            const int*   __restrict__ aug_choice,
                            const int*   __restrict__ slight_choice) {
    int p = blockIdx.x * 256 + threadIdx.x;
    if (p >= NPATCH) return;

    float q = 0.f, m = 0.f;
#pragma unroll
    for (int b = 0; b < NB; ++b) {
        q += g_qual [b * NPATCH + p];
        m += g_pmean[b * NPATCH + p];
    }
    q *= (1.0f / NB);
    m *= (1.0f / NB);

    bool low    = q < 0.7f;
    bool strong = low  && (r_strong[p] < 0.8f);
    bool drop   = low  && (q < 0.3f) && (r_drop[p] < 0.1f);
    bool els    = !low && (r_else[p] < 0.3f);

    int code = 0;
    if (strong) code = aug_choice[p] + 1;      // 1..4
    if (els)    code = slight_choice[p] + 5;   // 5..6
    if (drop)   code = 7;

    float scale = 0.f;
    if      (code == 1) scale = 0.1f;
    else if (code == 3) scale = bright_f[p];
    else if (code == 4) scale = contrast_f[p];
    else if (code == 5) scale = 0.05f;
    else if (code == 6) scale = slight_f[p];

    g_code [p] = code;
    g_scale[p] = scale;
    g_mpp  [p] = m;
}

__device__ __forceinline__ float clamp01(float x) {
    return fminf(fmaxf(x, 0.0f), 1.0f);
}

// ---------------------------------------------------------------------------
// Kernel 3: apply. Block 128 threads x float4 = 512-col, 16-row strip.
// Reversed (sy,b) traversal so apply starts on the img tail that stats
// left resident in L2 (img ~= L2 capacity). Non-blur outputs are emitted in
// the load pass; blur patches do a second smem-only pass.
// ---------------------------------------------------------------------------
__global__ void apply_kernel(const float4* __restrict__ img,
                             const float4* __restrict__ noise,
                             float4* __restrict__ out) {
    __shared__ float tile[PS][512];
    __shared__ int   s_code[32];
    __shared__ float s_scale[32];
    __shared__ float s_mpp[32];

    const int tx = threadIdx.x;
    const int bx = blockIdx.x;                 // strip half 0..1
    const int sy = (PH - 1) - blockIdx.y;      // reversed patch row
    const int b  = (NB - 1) - blockIdx.z;      // reversed batch

    const size_t base = ((size_t)b * IH + (size_t)sy * PS) * ROWF4 + bx * 128 + tx;

    if (tx < 32) {
        int p = sy * PW + bx * 32 + tx;
        s_code [tx] = g_code [p];
        s_scale[tx] = g_scale[p];
        s_mpp  [tx] = g_mpp  [p];
    }
    __syncthreads();

    const int   lp    = tx >> 2;               // local patch 0..31
    const int   code  = s_code[lp];
    const float scale = s_scale[lp];
    const float mpp   = s_mpp[lp];

    // Pass 1: load, stash in smem, emit all non-blur outputs immediately.
#pragma unroll
    for (int y = 0; y < PS; ++y) {
        float4 v = img[base + (size_t)y * ROWF4];
        reinterpret_cast<float4*>(tile[y])[tx] = v;
        if (code != 2) {
            float4 r;
            if (code == 0) {
                r = v;
            } else if (code == 7) {
                r = make_float4(0.f, 0.f, 0.f, 0.f);
            } else if (code == 1 || code == 5) {
                float4 nv = noise[base + (size_t)y * ROWF4];
                r.x = clamp01(fmaf(nv.x, scale, v.x));
                r.y = clamp01(fmaf(nv.y, scale, v.y));
                r.z = clamp01(fmaf(nv.z, scale, v.z));
                r.w = clamp01(fmaf(nv.w, scale, v.w));
            } else if (code == 3 || code == 6) {
                r.x = clamp01(v.x * scale);
                r.y = clamp01(v.y * scale);
                r.z = clamp01(v.z * scale);
                r.w = clamp01(v.w * scale);
            } else { // code == 4 (contrast)
                r.x = clamp01(fmaf(v.x - mpp, scale, mpp));
                r.y = clamp01(fmaf(v.y - mpp, scale, mpp));
                r.z = clamp01(fmaf(v.z - mpp, scale, mpp));
                r.w = clamp01(fmaf(v.w - mpp, scale, mpp));
            }
            out[base + (size_t)y * ROWF4] = r;
        }
    }
    __syncthreads();

    // Pass 2: 3x3 patch-confined blur for code==2 patches, from smem.
    if (code == 2) {
        const int colbase = tx * 4;            // col within 512-wide tile
        const int lx0     = (tx & 3) * 4;      // col within patch (0,4,8,12)
#pragma unroll
        for (int y = 0; y < PS; ++y) {
            float r[4];
#pragma unroll
            for (int j = 0; j < 4; ++j) {
                const int lx = lx0 + j;
                float sum = 0.f;
#pragma unroll
                for (int dy = -1; dy <= 1; ++dy) {
                    const int yy = y + dy;
                    if (yy < 0 || yy >= PS) continue;
#pragma unroll
                    for (int dx = -1; dx <= 1; ++dx) {
                        const int lxx = lx + dx;
                        if (lxx < 0 || lxx >= PS) continue;
                        sum += tile[yy][colbase + j + dx];
                    }
                }
                r[j] = sum * (1.0f / 9.0f);
            }
            out[base + (size_t)y * ROWF4] = make_float4(r[0], r[1], r[2], r[3]);
        }
    }
}

extern "C" void kernel_launch(void* const* d_in, const int* in_sizes, int n_in,
                              void* d_out, int out_size) {
    const float4* img          = (const float4*)d_in[0];
    const float4* noise        = (const float4*)d_in[1];
    const float* r_strong      = (const float*)d_in[2];
    const float* r_drop        = (const float*)d_in[3];
    const float* r_else        = (const float*)d_in[4];
    const float* bright_f      = (const float*)d_in[5];
    const float* contrast_f    = (const float*)d_in[6];
    const float* slight_f      = (const float*)d_in[7];
    const int*   aug_choice    = (const int*)d_in[8];
    const int*   slight_choice = (const int*)d_in[9];
    float4* out = (float4*)d_out;

    stats_kernel<<<dim3(PH, NB), 256>>>(img);
    code_kernel<<<NPATCH / 256, 256>>>(r_strong, r_drop, r_else,
                                       bright_f, contrast_f, slight_f,
                                       aug_choice, slight_choice);
    apply_kernel<<<dim3(2, PH, NB), 128>>>(img, noise, out);
}

// round 3
// speedup vs baseline: 1.9536x; 1.9536x over previous
#include <cuda_runtime.h>
#include <math.h>

#define PS 16
#define PH 64
#define PW 64
#define NPATCH (PH*PW)
#define NB 32
#define IH 1024
#define IW 1024
#define ROWF4 (IW/4)

// Scratch (no device allocation allowed)
__device__ float g_qual [NB*NPATCH];
__device__ float g_pmean[NB*NPATCH];
__device__ int   g_code [NPATCH];
__device__ float g_scale[NPATCH];
__device__ float g_mpp  [NPATCH];

// ---------------------------------------------------------------------------
// Kernel 1: per-(batch, patch) quality + mean. float4 loads, REVERSED
// traversal so the img tail left in L2 matches apply's forward start.
// ---------------------------------------------------------------------------
__global__ void stats_kernel(const float4* __restrict__ img) {
    const int tx = threadIdx.x;
    const int sy = (PH - 1) - blockIdx.x;  // reversed patch row
    const int b  = (NB - 1) - blockIdx.y;  // reversed batch

    const float4* base = img + ((size_t)b * IH + (size_t)sy * PS) * ROWF4 + tx;

    float s = 0.f, ss = 0.f;
#pragma unroll
    for (int y = 0; y < PS; ++y) {
        float4 v = base[(size_t)y * ROWF4];
        s  += (v.x + v.y) + (v.z + v.w);
        ss  = fmaf(v.x, v.x, ss);
        ss  = fmaf(v.y, v.y, ss);
        ss  = fmaf(v.z, v.z, ss);
        ss  = fmaf(v.w, v.w, ss);
    }
#pragma unroll
    for (int off = 2; off >= 1; off >>= 1) {
        s  += __shfl_down_sync(0xffffffffu, s,  off, 4);
        ss += __shfl_down_sync(0xffffffffu, ss, off, 4);
    }
    if ((tx & 3) == 0) {
        float mean = s * (1.0f / 256.0f);
        float var  = (ss - s * s * (1.0f / 256.0f)) * (1.0f / 255.0f); // ddof=1
        var = fmaxf(var, 0.0f);
        float std_ = sqrtf(var);
        float iq   = 1.0f - 2.0f * fabsf(mean - 0.5f);
        float quality = (std_ + iq + var) * (1.0f / 3.0f);
        int p = sy * PW + (tx >> 2);
        g_qual [b * NPATCH + p] = quality;
        g_pmean[b * NPATCH + p] = mean;
    }
}

// ---------------------------------------------------------------------------
// Kernel 2: per-patch code/scale/mpp. Deterministic batch reduction.
// ---------------------------------------------------------------------------
__global__ void code_kernel(const float* __restrict__ r_strong,
                            const float* __restrict__ r_drop,
                            const float* __restrict__ r_else,
                            const float* __restrict__ bright_f,
                            const float* __restrict__ contrast_f,
                            const float* __restrict__ slight_f,
                            const int*   __restrict__ aug_choice,
                            const int*   __restrict__ slight_choice) {
    int p = blockIdx.x * 256 + threadIdx.x;
    if (p >= NPATCH) return;

    float q = 0.f, m = 0.f;
#pragma unroll
    for (int b = 0; b < NB; ++b) {
        q += g_qual [b * NPATCH + p];
        m += g_pmean[b * NPATCH + p];
    }
    q *= (1.0f / NB);
    m *= (1.0f / NB);

    bool low    = q < 0.7f;
    bool strong = low  && (r_strong[p] < 0.8f);
    bool drop   = low  && (q < 0.3f) && (r_drop[p] < 0.1f);
    bool els    = !low && (r_else[p] < 0.3f);

    int code = 0;
    if (strong) code = aug_choice[p] + 1;      // 1..4
    if (els)    code = slight_choice[p] + 5;   // 5..6
    if (drop)   code = 7;

    float scale = 0.f;
    if      (code == 1) scale = 0.1f;
    else if (code == 3) scale = bright_f[p];
    else if (code == 4) scale = contrast_f[p];
    else if (code == 5) scale = 0.05f;
    else if (code == 6) scale = slight_f[p];

    g_code [p] = code;
    g_scale[p] = scale;
    g_mpp  [p] = m;
}

__device__ __forceinline__ float clamp01(float x) {
    return fminf(fmaxf(x, 0.0f), 1.0f);
}

// ---------------------------------------------------------------------------
// Kernel 3: apply. Single pass, register-resident, no smem, no syncthreads.
// Thread owns one column of a 16x256 strip: 16 front-batched loads (MLP=16),
// compute, 16 stores. Blur: vertical neighbors in registers, horizontal via
// 16-wide shfl (group-masked; patch = 16 consecutive lanes).
// ---------------------------------------------------------------------------
__global__ void apply_kernel(const float* __restrict__ img,
                             const float* __restrict__ noise,
                             float* __restrict__ out) {
    const int tx = threadIdx.x;
    const int x  = blockIdx.x * 256 + tx;
    const int sy = blockIdx.y;
    const int b  = blockIdx.z;

    const size_t base = ((size_t)b * IH + (size_t)sy * PS) * IW + x;

    // Front-batched loads: 16 independent LDGs -> high MLP.
    float v[PS];
#pragma unroll
    for (int y = 0; y < PS; ++y)
        v[y] = img[base + (size_t)y * IW];

    const int   p     = sy * PW + (x >> 4);
    const int   code  = g_code[p];            // 16-lane broadcast load
    const float scale = g_scale[p];
    const float mpp   = g_mpp[p];
    const int   lx    = tx & 15;
    // shfl member mask = this thread's 16-lane group within the warp
    const unsigned gmask = 0xFFFFu << (tx & 16);

    float r[PS];
    if (code == 0) {
#pragma unroll
        for (int y = 0; y < PS; ++y) r[y] = v[y];
    } else if (code == 7) {
#pragma unroll
        for (int y = 0; y < PS; ++y) r[y] = 0.0f;
    } else if (code == 2) {
        // 3x3 zero-padded blur confined to the patch.
        float hs[PS];
#pragma unroll
        for (int y = 0; y < PS; ++y) {
            float l = __shfl_up_sync  (gmask, v[y], 1, 16);
            float rr = __shfl_down_sync(gmask, v[y], 1, 16);
            if (lx == 0)  l  = 0.0f;
            if (lx == 15) rr = 0.0f;
            hs[y] = v[y] + l + rr;
        }
#pragma unroll
        for (int y = 0; y < PS; ++y) {
            float sum = hs[y];
            if (y > 0)      sum += hs[y - 1];
            if (y < PS - 1) sum += hs[y + 1];
            r[y] = sum * (1.0f / 9.0f);
        }
    } else if (code == 1 || code == 5) {
        float n[PS];
#pragma unroll
        for (int y = 0; y < PS; ++y)
            n[y] = noise[base + (size_t)y * IW];
#pragma unroll
        for (int y = 0; y < PS; ++y)
            r[y] = clamp01(fmaf(n[y], scale, v[y]));
    } else if (code == 3 || code == 6) {
#pragma unroll
        for (int y = 0; y < PS; ++y)
            r[y] = clamp01(v[y] * scale);
    } else { // code == 4 (contrast)
#pragma unroll
        for (int y = 0; y < PS; ++y)
            r[y] = clamp01(fmaf(v[y] - mpp, scale, mpp));
    }

    // Common store epilogue: streaming stores, no L2 pollution.
#pragma unroll
    for (int y = 0; y < PS; ++y)
        __stcs(&out[base + (size_t)y * IW], r[y]);
}

extern "C" void kernel_launch(void* const* d_in, const int* in_sizes, int n_in,
                              void* d_out, int out_size) {
    const float4* img4         = (const float4*)d_in[0];
    const float* img           = (const float*)d_in[0];
    const float* noise         = (const float*)d_in[1];
    const float* r_strong      = (const float*)d_in[2];
    const float* r_drop        = (const float*)d_in[3];
    const float* r_else        = (const float*)d_in[4];
    const float* bright_f      = (const float*)d_in[5];
    const float* contrast_f    = (const float*)d_in[6];
    const float* slight_f      = (const float*)d_in[7];
    const int*   aug_choice    = (const int*)d_in[8];
    const int*   slight_choice = (const int*)d_in[9];
    float* out = (float*)d_out;

    stats_kernel<<<dim3(PH, NB), 256>>>(img4);
    code_kernel<<<NPATCH / 256, 256>>>(r_strong, r_drop, r_else,
                                       bright_f, contrast_f, slight_f,
                                       aug_choice, slight_choice);
    apply_kernel<<<dim3(IW / 256, PH, NB), 256>>>(img, noise, out);
}